// round 2
// baseline (speedup 1.0000x reference)
#include <cuda_runtime.h>
#include <math.h>

#define L   12288
#define BB  8
#define NI  24                    // i-chunks
#define CHUNK (L / NI)            // 512 rows per chunk
#define TI  256                   // predicts smem tile rows
#define THREADS 256
#define CPT 4                     // columns per thread (int4 mask)
#define GX  (L / (THREADS * CPT)) // 12 column-blocks
#define GX2 (L / 128)             // 96 pass2 blocks

// Scratch (static device globals — allocation-free)
__device__ float g_part[NI][BB][L];   // partial candidate sums
__device__ float g_cnt[NI][L];        // partial counts
__device__ float g_bpart[GX2][BB];    // pass2 per-block squared-diff sums

// ---------------------------------------------------------------------------
// Pass 1: partial  cand[b][j] = sum_{i in chunk} mask[i][j] * adj[i][j] * p[b][i]
//         partial  cnt[j]     = sum_{i in chunk} mask[i][j]
// ---------------------------------------------------------------------------
__global__ __launch_bounds__(THREADS)
void pass1_kernel(const float* __restrict__ predicts,
                  const float* __restrict__ adj,
                  const int* __restrict__ mask) {
    __shared__ float sp[BB][TI];      // predicts tile, broadcast-friendly layout

    const int t     = threadIdx.x;
    const int j0    = blockIdx.x * (THREADS * CPT) + t * CPT;  // first of 4 cols
    const int chunk = blockIdx.y;
    const int i0    = chunk * CHUNK;

    float acc[CPT][BB];
    float cnt[CPT];
#pragma unroll
    for (int c = 0; c < CPT; ++c) {
        cnt[c] = 0.f;
#pragma unroll
        for (int b = 0; b < BB; ++b) acc[c][b] = 0.f;
    }

    for (int tile = 0; tile < CHUNK; tile += TI) {
        const int ibase = i0 + tile;
        __syncthreads();
#pragma unroll
        for (int b = 0; b < BB; ++b)
            sp[b][t] = predicts[b * L + ibase + t];
        __syncthreads();

        const int* mp = mask + (size_t)ibase * L + j0;
#pragma unroll 4
        for (int ii = 0; ii < TI; ++ii) {
            const int4 m4 = *(const int4*)mp;   // 4 mask int32s
            mp += L;
            if (m4.x | m4.y | m4.z | m4.w) {
                const float* arow = adj + (size_t)(ibase + ii) * L + j0;
                const float pv = 1.0f;  (void)pv;
                int mv[CPT] = {m4.x, m4.y, m4.z, m4.w};
#pragma unroll
                for (int c = 0; c < CPT; ++c) {
                    if (mv[c]) {
                        const float a = arow[c];
                        cnt[c] += 1.f;
#pragma unroll
                        for (int b = 0; b < BB; ++b)
                            acc[c][b] = fmaf(sp[b][ii], a, acc[c][b]);
                    }
                }
            }
        }
    }

#pragma unroll
    for (int c = 0; c < CPT; ++c) {
        g_cnt[chunk][j0 + c] = cnt[c];
#pragma unroll
        for (int b = 0; b < BB; ++b)
            g_part[chunk][b][j0 + c] = acc[c][b];
    }
}

// ---------------------------------------------------------------------------
// Pass 2: per column j: finalize candidates, diff = p - sim @ cand,
//         accumulate per-b sum of diff^2 into per-block partials.
// ---------------------------------------------------------------------------
__global__ __launch_bounds__(128)
void pass2_kernel(const float* __restrict__ predicts,
                  const float* __restrict__ sim,
                  const int* __restrict__ mask) {
    __shared__ float ssim[BB * BB];
    __shared__ float red[128];

    const int t = threadIdx.x;
    if (t < BB * BB) ssim[t] = sim[t];
    __syncthreads();

    const int j = blockIdx.x * 128 + t;

    float acc[BB];
    float cnt = 0.f;
#pragma unroll
    for (int b = 0; b < BB; ++b) acc[b] = 0.f;

#pragma unroll
    for (int c = 0; c < NI; ++c) {
        cnt += g_cnt[c][j];
#pragma unroll
        for (int b = 0; b < BB; ++b) acc[b] += g_part[c][b][j];
    }

    const float mjj = mask[(size_t)j * L + j] ? 1.f : 0.f;
    const float add = 1.f - mjj;           // identity-diagonal correction
    cnt += add;
    const float inv = 1.f / cnt;

    float p[BB], cand[BB];
#pragma unroll
    for (int b = 0; b < BB; ++b) p[b] = predicts[b * L + j];
#pragma unroll
    for (int b = 0; b < BB; ++b) cand[b] = (acc[b] + p[b] * add) * inv;

    float ss[BB];
#pragma unroll
    for (int b = 0; b < BB; ++b) {
        float d = p[b];
#pragma unroll
        for (int k = 0; k < BB; ++k) d -= ssim[b * BB + k] * cand[k];
        ss[b] = d * d;
    }

    // block reduction per b (deterministic — no atomics)
#pragma unroll
    for (int b = 0; b < BB; ++b) {
        red[t] = ss[b];
        __syncthreads();
        for (int s = 64; s > 0; s >>= 1) {
            if (t < s) red[t] += red[t + s];
            __syncthreads();
        }
        if (t == 0) g_bpart[blockIdx.x][b] = red[0];
        __syncthreads();
    }
}

// ---------------------------------------------------------------------------
// Pass 3: final reduce: norms = sqrt(sumsq), valid mask, mean over valid.
// ---------------------------------------------------------------------------
__global__ __launch_bounds__(256)
void pass3_kernel(const float* __restrict__ sim, float* __restrict__ out) {
    __shared__ float norms[BB];
    const int w    = threadIdx.x >> 5;
    const int lane = threadIdx.x & 31;

    if (w < BB) {
        float s = 0.f;
        for (int i = lane; i < GX2; i += 32) s += g_bpart[i][w];
#pragma unroll
        for (int o = 16; o > 0; o >>= 1) s += __shfl_down_sync(0xffffffffu, s, o);
        if (lane == 0) norms[w] = sqrtf(s);
    }
    __syncthreads();

    if (threadIdx.x == 0) {
        float total = 0.f, c = 0.f;
        for (int b = 0; b < BB; ++b) {
            float rs = 0.f;
            for (int k = 0; k < BB; ++k) rs += sim[b * BB + k];
            if (rs != 0.f) { c += 1.f; total += norms[b]; }
        }
        out[0] = (c == 0.f) ? 0.f : total / fmaxf(c, 1.f);
    }
}

// ---------------------------------------------------------------------------
extern "C" void kernel_launch(void* const* d_in, const int* in_sizes, int n_in,
                              void* d_out, int out_size) {
    (void)in_sizes; (void)n_in; (void)out_size;
    const float* predicts = (const float*)d_in[0];   // [8, L]
    const float* sim      = (const float*)d_in[1];   // [8, 8]
    const float* adj      = (const float*)d_in[2];   // [L, L]
    const int*   mask     = (const int*)d_in[3];     // [L, L] bool->int32
    float* out = (float*)d_out;

    dim3 g1(GX, NI);
    pass1_kernel<<<g1, THREADS>>>(predicts, adj, mask);
    pass2_kernel<<<GX2, 128>>>(predicts, sim, mask);
    pass3_kernel<<<1, 256>>>(sim, out);
}

// round 3
// speedup vs baseline: 2.4224x; 2.4224x over previous
#include <cuda_runtime.h>
#include <math.h>

#define L   12288
#define BB  8
#define NI  48                    // i-chunks
#define CHUNK (L / NI)            // 256 rows per chunk
#define TI  256                   // predicts smem tile rows (== CHUNK)
#define THREADS 256
#define CPT 2                     // columns per thread (int2 mask)
#define GX  (L / (THREADS * CPT)) // 24 column-blocks
#define RB  8                     // mask row batch (MLP)
#define GX2 (L / 128)             // 96 pass2 blocks

// Scratch (static device globals — allocation-free)
__device__ float g_part[NI][BB][L];   // partial candidate sums   (~18.9 MB)
__device__ float g_cnt[NI][L];        // partial counts           (~2.4 MB)
__device__ float g_bpart[GX2][BB];    // pass2 per-block squared-diff sums

// ---------------------------------------------------------------------------
// Pass 1: partial  cand[b][j] = sum_{i in chunk} mask[i][j] * adj[i][j] * p[b][i]
//         partial  cnt[j]     = sum_{i in chunk} mask[i][j]
// ---------------------------------------------------------------------------
__global__ __launch_bounds__(THREADS, 4)
void pass1_kernel(const float* __restrict__ predicts,
                  const float* __restrict__ adj,
                  const int* __restrict__ mask) {
    __shared__ float sp[BB][TI];      // predicts tile, broadcast layout

    const int t     = threadIdx.x;
    const int j0    = blockIdx.x * (THREADS * CPT) + t * CPT;  // first of 2 cols
    const int chunk = blockIdx.y;
    const int i0    = chunk * CHUNK;

    float acc0[BB], acc1[BB];
    float cnt0 = 0.f, cnt1 = 0.f;
#pragma unroll
    for (int b = 0; b < BB; ++b) { acc0[b] = 0.f; acc1[b] = 0.f; }

    // load predicts tile (CHUNK == TI, single tile)
#pragma unroll
    for (int b = 0; b < BB; ++b)
        sp[b][t] = predicts[b * L + i0 + t];
    __syncthreads();

    const int* mp = mask + (size_t)i0 * L + j0;

    for (int ii = 0; ii < TI; ii += RB) {
        // front-batched independent mask loads (MLP = RB)
        int2 m[RB];
#pragma unroll
        for (int r = 0; r < RB; ++r)
            m[r] = __ldcs((const int2*)(mp + (size_t)r * L));
        mp += (size_t)RB * L;

#pragma unroll
        for (int r = 0; r < RB; ++r) {
            if (m[r].x | m[r].y) {
                const float pvrow = sp[0][ii + r]; (void)pvrow;
                const float* arow = adj + (size_t)(i0 + ii + r) * L + j0;
                if (m[r].x) {
                    const float a = __ldcs(arow);
                    cnt0 += 1.f;
#pragma unroll
                    for (int b = 0; b < BB; ++b)
                        acc0[b] = fmaf(sp[b][ii + r], a, acc0[b]);
                }
                if (m[r].y) {
                    const float a = __ldcs(arow + 1);
                    cnt1 += 1.f;
#pragma unroll
                    for (int b = 0; b < BB; ++b)
                        acc1[b] = fmaf(sp[b][ii + r], a, acc1[b]);
                }
            }
        }
    }

    g_cnt[chunk][j0]     = cnt0;
    g_cnt[chunk][j0 + 1] = cnt1;
#pragma unroll
    for (int b = 0; b < BB; ++b) {
        g_part[chunk][b][j0]     = acc0[b];
        g_part[chunk][b][j0 + 1] = acc1[b];
    }
}

// ---------------------------------------------------------------------------
// Pass 2: per column j: finalize candidates, diff = p - sim @ cand,
//         accumulate per-b sum of diff^2 into per-block partials.
// ---------------------------------------------------------------------------
__global__ __launch_bounds__(128)
void pass2_kernel(const float* __restrict__ predicts,
                  const float* __restrict__ sim,
                  const int* __restrict__ mask) {
    __shared__ float ssim[BB * BB];
    __shared__ float red[128];

    const int t = threadIdx.x;
    if (t < BB * BB) ssim[t] = sim[t];
    __syncthreads();

    const int j = blockIdx.x * 128 + t;

    float acc[BB];
    float cnt = 0.f;
#pragma unroll
    for (int b = 0; b < BB; ++b) acc[b] = 0.f;

    for (int c = 0; c < NI; ++c) {
        cnt += g_cnt[c][j];
#pragma unroll
        for (int b = 0; b < BB; ++b) acc[b] += g_part[c][b][j];
    }

    const float mjj = mask[(size_t)j * L + j] ? 1.f : 0.f;
    const float add = 1.f - mjj;           // identity-diagonal correction
    cnt += add;
    const float inv = 1.f / cnt;

    float p[BB], cand[BB];
#pragma unroll
    for (int b = 0; b < BB; ++b) p[b] = predicts[b * L + j];
#pragma unroll
    for (int b = 0; b < BB; ++b) cand[b] = (acc[b] + p[b] * add) * inv;

    float ss[BB];
#pragma unroll
    for (int b = 0; b < BB; ++b) {
        float d = p[b];
#pragma unroll
        for (int k = 0; k < BB; ++k) d -= ssim[b * BB + k] * cand[k];
        ss[b] = d * d;
    }

    // block reduction per b (deterministic — no atomics)
#pragma unroll
    for (int b = 0; b < BB; ++b) {
        red[t] = ss[b];
        __syncthreads();
        for (int s = 64; s > 0; s >>= 1) {
            if (t < s) red[t] += red[t + s];
            __syncthreads();
        }
        if (t == 0) g_bpart[blockIdx.x][b] = red[0];
        __syncthreads();
    }
}

// ---------------------------------------------------------------------------
// Pass 3: final reduce: norms = sqrt(sumsq), valid mask, mean over valid.
// ---------------------------------------------------------------------------
__global__ __launch_bounds__(256)
void pass3_kernel(const float* __restrict__ sim, float* __restrict__ out) {
    __shared__ float norms[BB];
    const int w    = threadIdx.x >> 5;
    const int lane = threadIdx.x & 31;

    if (w < BB) {
        float s = 0.f;
        for (int i = lane; i < GX2; i += 32) s += g_bpart[i][w];
#pragma unroll
        for (int o = 16; o > 0; o >>= 1) s += __shfl_down_sync(0xffffffffu, s, o);
        if (lane == 0) norms[w] = sqrtf(s);
    }
    __syncthreads();

    if (threadIdx.x == 0) {
        float total = 0.f, c = 0.f;
        for (int b = 0; b < BB; ++b) {
            float rs = 0.f;
            for (int k = 0; k < BB; ++k) rs += sim[b * BB + k];
            if (rs != 0.f) { c += 1.f; total += norms[b]; }
        }
        out[0] = (c == 0.f) ? 0.f : total / fmaxf(c, 1.f);
    }
}

// ---------------------------------------------------------------------------
extern "C" void kernel_launch(void* const* d_in, const int* in_sizes, int n_in,
                              void* d_out, int out_size) {
    (void)in_sizes; (void)n_in; (void)out_size;
    const float* predicts = (const float*)d_in[0];   // [8, L]
    const float* sim      = (const float*)d_in[1];   // [8, 8]
    const float* adj      = (const float*)d_in[2];   // [L, L]
    const int*   mask     = (const int*)d_in[3];     // [L, L] bool->int32
    float* out = (float*)d_out;

    dim3 g1(GX, NI);
    pass1_kernel<<<g1, THREADS>>>(predicts, adj, mask);
    pass2_kernel<<<GX2, 128>>>(predicts, sim, mask);
    pass3_kernel<<<1, 256>>>(sim, out);
}

// round 4
// speedup vs baseline: 2.4828x; 1.0250x over previous
#include <cuda_runtime.h>
#include <math.h>

#define L   12288
#define BB  8
#define NI  48                    // i-chunks
#define CHUNK (L / NI)            // 256 rows per chunk
#define THREADS 256
#define GX  (L / THREADS)         // 48 column-blocks (1 col/thread)
#define RB  8                     // mask row batch (MLP)
#define GX2 (L / 32)              // 384 pass2 blocks

// Scratch (static device globals — allocation-free)
__device__ float g_part[NI][BB][L];   // partial candidate sums (~18.9 MB)
__device__ float g_cnt[NI][L];        // partial counts
__device__ float g_bpart[GX2][BB];    // pass2 per-block squared-diff sums

// ---------------------------------------------------------------------------
// Pass 1: partial  cand[b][j] = sum_{i in chunk} mask[i][j] * adj[i][j] * p[b][i]
//         partial  cnt[j]     = sum_{i in chunk} mask[i][j]
// ---------------------------------------------------------------------------
__global__ __launch_bounds__(THREADS, 6)
void pass1_kernel(const float* __restrict__ predicts,
                  const float* __restrict__ adj,
                  const int* __restrict__ mask) {
    __shared__ float sp[BB][CHUNK];   // predicts tile, broadcast layout

    const int t     = threadIdx.x;
    const int j     = blockIdx.x * THREADS + t;   // this thread's column
    const int chunk = blockIdx.y;
    const int i0    = chunk * CHUNK;

    float acc[BB];
    float cnt = 0.f;
#pragma unroll
    for (int b = 0; b < BB; ++b) acc[b] = 0.f;

    // load predicts tile (CHUNK == 256 == THREADS, single shot)
#pragma unroll
    for (int b = 0; b < BB; ++b)
        sp[b][t] = predicts[b * L + i0 + t];
    __syncthreads();

    const int* mp = mask + (size_t)i0 * L + j;

    for (int ii = 0; ii < CHUNK; ii += RB) {
        // front-batched independent mask loads (MLP = RB)
        int m[RB];
#pragma unroll
        for (int r = 0; r < RB; ++r)
            m[r] = __ldcs(mp + (size_t)r * L);
        mp += (size_t)RB * L;

#pragma unroll
        for (int r = 0; r < RB; ++r) {
            if (m[r]) {
                const float a = __ldcs(adj + (size_t)(i0 + ii + r) * L + j);
                cnt += 1.f;
#pragma unroll
                for (int b = 0; b < BB; ++b)
                    acc[b] = fmaf(sp[b][ii + r], a, acc[b]);
            }
        }
    }

    g_cnt[chunk][j] = cnt;
#pragma unroll
    for (int b = 0; b < BB; ++b)
        g_part[chunk][b][j] = acc[b];
}

// ---------------------------------------------------------------------------
// Pass 2: thread = (b, j) pair. 256 threads = 8 b-groups x 32 j-lanes.
// Finalize candidates, exchange via smem, diff = p - sim @ cand,
// per-(block,b) squared-diff partials via warp shuffles.
// ---------------------------------------------------------------------------
__global__ __launch_bounds__(256)
void pass2_kernel(const float* __restrict__ predicts,
                  const float* __restrict__ sim,
                  const int* __restrict__ mask) {
    __shared__ float ssim[BB * BB];
    __shared__ float scand[BB][33];
    __shared__ float sadd[32], sinv[32];

    const int t  = threadIdx.x;
    const int b  = t >> 5;
    const int jl = t & 31;
    const int j  = blockIdx.x * 32 + jl;

    if (t < BB * BB) ssim[t] = sim[t];

    // b==0 group computes counts + diagonal correction for the 32 columns
    if (b == 0) {
        float cnt = 0.f;
#pragma unroll
        for (int c = 0; c < NI; ++c) cnt += g_cnt[c][j];
        const float mjj = mask[(size_t)j * (L + 1)] ? 1.f : 0.f;
        const float add = 1.f - mjj;
        sadd[jl] = add;
        sinv[jl] = 1.f / (cnt + add);
    }

    // every (b, j) thread reduces its partials
    float acc = 0.f;
#pragma unroll
    for (int c = 0; c < NI; ++c) acc += g_part[c][b][j];
    const float p = predicts[b * L + j];
    __syncthreads();

    const float cand = (acc + p * sadd[jl]) * sinv[jl];
    scand[b][jl] = cand;
    __syncthreads();

    float d = p;
#pragma unroll
    for (int k = 0; k < BB; ++k) d -= ssim[b * BB + k] * scand[k][jl];
    float ss = d * d;

    // reduce across the 32 j-lanes of this b-group (one warp)
#pragma unroll
    for (int o = 16; o > 0; o >>= 1) ss += __shfl_down_sync(0xffffffffu, ss, o);
    if (jl == 0) g_bpart[blockIdx.x][b] = ss;
}

// ---------------------------------------------------------------------------
// Pass 3: final reduce: norms = sqrt(sumsq), valid mask, mean over valid.
// ---------------------------------------------------------------------------
__global__ __launch_bounds__(256)
void pass3_kernel(const float* __restrict__ sim, float* __restrict__ out) {
    __shared__ float norms[BB];
    const int w    = threadIdx.x >> 5;
    const int lane = threadIdx.x & 31;

    if (w < BB) {
        float s = 0.f;
        for (int i = lane; i < GX2; i += 32) s += g_bpart[i][w];
#pragma unroll
        for (int o = 16; o > 0; o >>= 1) s += __shfl_down_sync(0xffffffffu, s, o);
        if (lane == 0) norms[w] = sqrtf(s);
    }
    __syncthreads();

    if (threadIdx.x == 0) {
        float total = 0.f, c = 0.f;
        for (int b = 0; b < BB; ++b) {
            float rs = 0.f;
            for (int k = 0; k < BB; ++k) rs += sim[b * BB + k];
            if (rs != 0.f) { c += 1.f; total += norms[b]; }
        }
        out[0] = (c == 0.f) ? 0.f : total / fmaxf(c, 1.f);
    }
}

// ---------------------------------------------------------------------------
extern "C" void kernel_launch(void* const* d_in, const int* in_sizes, int n_in,
                              void* d_out, int out_size) {
    (void)in_sizes; (void)n_in; (void)out_size;
    const float* predicts = (const float*)d_in[0];   // [8, L]
    const float* sim      = (const float*)d_in[1];   // [8, 8]
    const float* adj      = (const float*)d_in[2];   // [L, L]
    const int*   mask     = (const int*)d_in[3];     // [L, L] bool->int32
    float* out = (float*)d_out;

    dim3 g1(GX, NI);
    pass1_kernel<<<g1, THREADS>>>(predicts, adj, mask);
    pass2_kernel<<<GX2, 256>>>(predicts, sim, mask);
    pass3_kernel<<<1, 256>>>(sim, out);
}

// round 6
// speedup vs baseline: 2.6787x; 1.0789x over previous
#include <cuda_runtime.h>
#include <math.h>

#define L   12288
#define BB  8
#define NI  48                    // i-chunks
#define CHUNK (L / NI)            // 256 rows per chunk
#define THREADS 256
#define GX  (L / THREADS)         // 48 column-blocks (1 col/thread)
#define RB  8                     // mask row batch (MLP)
#define GX2 (L / 32)              // 384 pass2 blocks

// Scratch (static device globals — allocation-free)
__device__ float g_part[NI][BB][L];   // partial candidate sums (~18.9 MB)
__device__ float g_cnt[NI][L];        // partial counts
__device__ float g_bpart[GX2][BB];    // pass2 per-block squared-diff sums

// ---------------------------------------------------------------------------
// Pass 1: partial  cand[b][j] = sum_{i in chunk} mask[i][j] * adj[i][j] * p[b][i]
//         partial  cnt[j]     = sum_{i in chunk} mask[i][j]
// predicts tile transposed: sp[i][b] -> one taken row costs 2x LDS.128.
// ---------------------------------------------------------------------------
__global__ __launch_bounds__(THREADS, 6)
void pass1_kernel(const float* __restrict__ predicts,
                  const float* __restrict__ adj,
                  const int* __restrict__ mask) {
    __shared__ float sp[CHUNK][BB];   // row-contiguous: 32B per row

    const int t     = threadIdx.x;
    const int j     = blockIdx.x * THREADS + t;   // this thread's column
    const int chunk = blockIdx.y;
    const int i0    = chunk * CHUNK;

    float acc[BB];
    float cnt = 0.f;
#pragma unroll
    for (int b = 0; b < BB; ++b) acc[b] = 0.f;

    // load predicts tile transposed (CHUNK == 256 == THREADS)
#pragma unroll
    for (int b = 0; b < BB; ++b)
        sp[t][b] = predicts[b * L + i0 + t];
    __syncthreads();

    const int* mp = mask + (size_t)i0 * L + j;

    for (int ii = 0; ii < CHUNK; ii += RB) {
        // front-batched independent mask loads (MLP = RB)
        int m[RB];
#pragma unroll
        for (int r = 0; r < RB; ++r)
            m[r] = __ldcs(mp + (size_t)r * L);
        mp += (size_t)RB * L;

#pragma unroll
        for (int r = 0; r < RB; ++r) {
            if (m[r]) {
                const float a = __ldcs(adj + (size_t)(i0 + ii + r) * L + j);
                cnt += 1.f;
                const float4 lo = *(const float4*)&sp[ii + r][0];
                const float4 hi = *(const float4*)&sp[ii + r][4];
                acc[0] = fmaf(lo.x, a, acc[0]);
                acc[1] = fmaf(lo.y, a, acc[1]);
                acc[2] = fmaf(lo.z, a, acc[2]);
                acc[3] = fmaf(lo.w, a, acc[3]);
                acc[4] = fmaf(hi.x, a, acc[4]);
                acc[5] = fmaf(hi.y, a, acc[5]);
                acc[6] = fmaf(hi.z, a, acc[6]);
                acc[7] = fmaf(hi.w, a, acc[7]);
            }
        }
    }

    g_cnt[chunk][j] = cnt;
#pragma unroll
    for (int b = 0; b < BB; ++b)
        g_part[chunk][b][j] = acc[b];
}

// ---------------------------------------------------------------------------
// Pass 2: thread = (b, j) pair. 256 threads = 8 b-groups x 32 j-lanes.
// ---------------------------------------------------------------------------
__global__ __launch_bounds__(256)
void pass2_kernel(const float* __restrict__ predicts,
                  const float* __restrict__ sim,
                  const int* __restrict__ mask) {
    __shared__ float ssim[BB * BB];
    __shared__ float scand[BB][33];
    __shared__ float sadd[32], sinv[32];

    const int t  = threadIdx.x;
    const int b  = t >> 5;
    const int jl = t & 31;
    const int j  = blockIdx.x * 32 + jl;

    if (t < BB * BB) ssim[t] = sim[t];

    if (b == 0) {
        float cnt = 0.f;
#pragma unroll
        for (int c = 0; c < NI; ++c) cnt += g_cnt[c][j];
        const float mjj = mask[(size_t)j * (L + 1)] ? 1.f : 0.f;
        const float add = 1.f - mjj;
        sadd[jl] = add;
        sinv[jl] = 1.f / (cnt + add);
    }

    float acc = 0.f;
#pragma unroll
    for (int c = 0; c < NI; ++c) acc += g_part[c][b][j];
    const float p = predicts[b * L + j];
    __syncthreads();

    const float cand = (acc + p * sadd[jl]) * sinv[jl];
    scand[b][jl] = cand;
    __syncthreads();

    float d = p;
#pragma unroll
    for (int k = 0; k < BB; ++k) d -= ssim[b * BB + k] * scand[k][jl];
    float ss = d * d;

#pragma unroll
    for (int o = 16; o > 0; o >>= 1) ss += __shfl_down_sync(0xffffffffu, ss, o);
    if (jl == 0) g_bpart[blockIdx.x][b] = ss;
}

// ---------------------------------------------------------------------------
// Pass 3: final reduce: norms = sqrt(sumsq), valid mask, mean over valid.
// ---------------------------------------------------------------------------
__global__ __launch_bounds__(256)
void pass3_kernel(const float* __restrict__ sim, float* __restrict__ out) {
    __shared__ float norms[BB];
    const int w    = threadIdx.x >> 5;
    const int lane = threadIdx.x & 31;

    if (w < BB) {
        float s = 0.f;
        for (int i = lane; i < GX2; i += 32) s += g_bpart[i][w];
#pragma unroll
        for (int o = 16; o > 0; o >>= 1) s += __shfl_down_sync(0xffffffffu, s, o);
        if (lane == 0) norms[w] = sqrtf(s);
    }
    __syncthreads();

    if (threadIdx.x == 0) {
        float total = 0.f, c = 0.f;
        for (int b = 0; b < BB; ++b) {
            float rs = 0.f;
            for (int k = 0; k < BB; ++k) rs += sim[b * BB + k];
            if (rs != 0.f) { c += 1.f; total += norms[b]; }
        }
        out[0] = (c == 0.f) ? 0.f : total / fmaxf(c, 1.f);
    }
}

// ---------------------------------------------------------------------------
extern "C" void kernel_launch(void* const* d_in, const int* in_sizes, int n_in,
                              void* d_out, int out_size) {
    (void)in_sizes; (void)n_in; (void)out_size;
    const float* predicts = (const float*)d_in[0];   // [8, L]
    const float* sim      = (const float*)d_in[1];   // [8, 8]
    const float* adj      = (const float*)d_in[2];   // [L, L]
    const int*   mask     = (const int*)d_in[3];     // [L, L] bool->int32
    float* out = (float*)d_out;

    dim3 g1(GX, NI);
    pass1_kernel<<<g1, THREADS>>>(predicts, adj, mask);
    pass2_kernel<<<GX2, 256>>>(predicts, sim, mask);
    pass3_kernel<<<1, 256>>>(sim, out);
}

// round 8
// speedup vs baseline: 3.2797x; 1.2243x over previous
#include <cuda_runtime.h>
#include <math.h>

#define L   12288
#define BB  8
#define NI  48                    // i-chunks
#define CHUNK (L / NI)            // 256 rows per chunk
#define THREADS 256
#define GX  (L / THREADS)         // 48 column-blocks (1 col/thread)
#define RB  8                     // mask row batch (MLP)
#define NB  (CHUNK / RB)          // 32 batches per chunk
#define GX2 (L / 32)              // 384 pass2 blocks

// Scratch (static device globals — allocation-free)
__device__ float g_part[NI][BB][L];   // partial candidate sums (~18.9 MB)
__device__ float g_cnt[NI][L];        // partial counts
__device__ float g_bpart[GX2][BB];    // pass2 per-block squared-diff sums

// ---------------------------------------------------------------------------
// Pass 1: partial  cand[b][j] = sum_{i in chunk} mask[i][j] * adj[i][j] * p[b][i]
//         partial  cnt[j]     = sum_{i in chunk} mask[i][j]
// Software-pipelined: next mask batch + predicated adj gather kept in flight
// while current batch's FMAs execute.
// ---------------------------------------------------------------------------
__global__ __launch_bounds__(THREADS, 5)
void pass1_kernel(const float* __restrict__ predicts,
                  const float* __restrict__ adj,
                  const int* __restrict__ mask) {
    __shared__ float sp[CHUNK][BB];   // row-contiguous: 32B per row

    const int t     = threadIdx.x;
    const int j     = blockIdx.x * THREADS + t;   // this thread's column
    const int chunk = blockIdx.y;
    const int i0    = chunk * CHUNK;

    float acc[BB];
    float cnt = 0.f;
#pragma unroll
    for (int b = 0; b < BB; ++b) acc[b] = 0.f;

    // load predicts tile transposed (CHUNK == 256 == THREADS)
#pragma unroll
    for (int b = 0; b < BB; ++b)
        sp[t][b] = predicts[b * L + i0 + t];
    __syncthreads();

    const int* mp = mask + (size_t)i0 * L + j;

    int m_cur[RB], m_nxt[RB];
    // prologue: batch 0 mask loads
#pragma unroll
    for (int r = 0; r < RB; ++r)
        m_cur[r] = __ldcs(mp + (size_t)r * L);

    for (int batch = 0; batch < NB; ++batch) {
        const int ii = batch * RB;

        // issue next batch's mask loads early (overlap with processing)
        if (batch + 1 < NB) {
            const int* mpn = mp + (size_t)RB * L;
#pragma unroll
            for (int r = 0; r < RB; ++r)
                m_nxt[r] = __ldcs(mpn + (size_t)r * L);
        }

        // predicated batched adj gather (back-to-back @P LDGs, high MLP)
        float a[RB];
#pragma unroll
        for (int r = 0; r < RB; ++r)
            a[r] = m_cur[r] ? __ldcs(adj + (size_t)(i0 + ii + r) * L + j) : 0.f;

        // consume
#pragma unroll
        for (int r = 0; r < RB; ++r) {
            if (m_cur[r]) {
                cnt += 1.f;
                const float4 lo = *(const float4*)&sp[ii + r][0];
                const float4 hi = *(const float4*)&sp[ii + r][4];
                acc[0] = fmaf(lo.x, a[r], acc[0]);
                acc[1] = fmaf(lo.y, a[r], acc[1]);
                acc[2] = fmaf(lo.z, a[r], acc[2]);
                acc[3] = fmaf(lo.w, a[r], acc[3]);
                acc[4] = fmaf(hi.x, a[r], acc[4]);
                acc[5] = fmaf(hi.y, a[r], acc[5]);
                acc[6] = fmaf(hi.z, a[r], acc[6]);
                acc[7] = fmaf(hi.w, a[r], acc[7]);
            }
        }

        mp += (size_t)RB * L;
#pragma unroll
        for (int r = 0; r < RB; ++r) m_cur[r] = m_nxt[r];
    }

    g_cnt[chunk][j] = cnt;
#pragma unroll
    for (int b = 0; b < BB; ++b)
        g_part[chunk][b][j] = acc[b];
}

// ---------------------------------------------------------------------------
// Pass 2: thread = (b, j) pair. 256 threads = 8 b-groups x 32 j-lanes.
// ---------------------------------------------------------------------------
__global__ __launch_bounds__(256)
void pass2_kernel(const float* __restrict__ predicts,
                  const float* __restrict__ sim,
                  const int* __restrict__ mask) {
    __shared__ float ssim[BB * BB];
    __shared__ float scand[BB][33];
    __shared__ float sadd[32], sinv[32];

    const int t  = threadIdx.x;
    const int b  = t >> 5;
    const int jl = t & 31;
    const int j  = blockIdx.x * 32 + jl;

    if (t < BB * BB) ssim[t] = sim[t];

    if (b == 0) {
        float cnt = 0.f;
#pragma unroll
        for (int c = 0; c < NI; ++c) cnt += g_cnt[c][j];
        const float mjj = mask[(size_t)j * (L + 1)] ? 1.f : 0.f;
        const float add = 1.f - mjj;
        sadd[jl] = add;
        sinv[jl] = 1.f / (cnt + add);
    }

    float acc = 0.f;
#pragma unroll
    for (int c = 0; c < NI; ++c) acc += g_part[c][b][j];
    const float p = predicts[b * L + j];
    __syncthreads();

    const float cand = (acc + p * sadd[jl]) * sinv[jl];
    scand[b][jl] = cand;
    __syncthreads();

    float d = p;
#pragma unroll
    for (int k = 0; k < BB; ++k) d -= ssim[b * BB + k] * scand[k][jl];
    float ss = d * d;

#pragma unroll
    for (int o = 16; o > 0; o >>= 1) ss += __shfl_down_sync(0xffffffffu, ss, o);
    if (jl == 0) g_bpart[blockIdx.x][b] = ss;
}

// ---------------------------------------------------------------------------
// Pass 3: final reduce: norms = sqrt(sumsq), valid mask, mean over valid.
// ---------------------------------------------------------------------------
__global__ __launch_bounds__(256)
void pass3_kernel(const float* __restrict__ sim, float* __restrict__ out) {
    __shared__ float norms[BB];
    const int w    = threadIdx.x >> 5;
    const int lane = threadIdx.x & 31;

    if (w < BB) {
        float s = 0.f;
        for (int i = lane; i < GX2; i += 32) s += g_bpart[i][w];
#pragma unroll
        for (int o = 16; o > 0; o >>= 1) s += __shfl_down_sync(0xffffffffu, s, o);
        if (lane == 0) norms[w] = sqrtf(s);
    }
    __syncthreads();

    if (threadIdx.x == 0) {
        float total = 0.f, c = 0.f;
        for (int b = 0; b < BB; ++b) {
            float rs = 0.f;
            for (int k = 0; k < BB; ++k) rs += sim[b * BB + k];
            if (rs != 0.f) { c += 1.f; total += norms[b]; }
        }
        out[0] = (c == 0.f) ? 0.f : total / fmaxf(c, 1.f);
    }
}

// ---------------------------------------------------------------------------
extern "C" void kernel_launch(void* const* d_in, const int* in_sizes, int n_in,
                              void* d_out, int out_size) {
    (void)in_sizes; (void)n_in; (void)out_size;
    const float* predicts = (const float*)d_in[0];   // [8, L]
    const float* sim      = (const float*)d_in[1];   // [8, 8]
    const float* adj      = (const float*)d_in[2];   // [L, L]
    const int*   mask     = (const int*)d_in[3];     // [L, L] bool->int32
    float* out = (float*)d_out;

    dim3 g1(GX, NI);
    pass1_kernel<<<g1, THREADS>>>(predicts, adj, mask);
    pass2_kernel<<<GX2, 256>>>(predicts, sim, mask);
    pass3_kernel<<<1, 256>>>(sim, out);
}

// round 10
// speedup vs baseline: 3.3238x; 1.0134x over previous
#include <cuda_runtime.h>
#include <math.h>

#define L   12288
#define BB  8
#define NI  48                    // i-chunks
#define CHUNK (L / NI)            // 256 rows per chunk
#define THREADS 256
#define GX  (L / THREADS)         // 48 column-blocks (1 col/thread)
#define RB  8                     // row batch (MLP)
#define NB  (CHUNK / RB)          // 32 batches per chunk
#define GX2 (L / 32)              // 384 pass2 blocks

// Scratch (static device globals — allocation-free)
__device__ float g_part[NI][BB][L];   // partial candidate sums (~18.9 MB)
__device__ float g_cnt[NI][L];        // partial counts
__device__ float g_bpart[GX2][BB];    // pass2 per-block squared-diff sums

// ---------------------------------------------------------------------------
// Pass 1: partial  cand[b][j] = sum_{i in chunk} mask[i][j] * adj[i][j] * p[b][i]
//         partial  cnt[j]     = sum_{i in chunk} mask[i][j]
// 3-stage pipeline: iter k issues adj-gather(k+1) + mask-load(k+2), consumes
// adj(k) fetched in the previous iteration. Predicate folded into the gathered
// value (-1 sentinel; adj >= 0 always).
// ---------------------------------------------------------------------------
__global__ __launch_bounds__(THREADS, 4)
void pass1_kernel(const float* __restrict__ predicts,
                  const float* __restrict__ adj,
                  const int* __restrict__ mask) {
    __shared__ float sp[CHUNK][BB];   // row-contiguous: 32B per row

    const int t     = threadIdx.x;
    const int j     = blockIdx.x * THREADS + t;   // this thread's column
    const int chunk = blockIdx.y;
    const int i0    = chunk * CHUNK;

    float acc[BB];
    float cnt = 0.f;
#pragma unroll
    for (int b = 0; b < BB; ++b) acc[b] = 0.f;

    // load predicts tile transposed (CHUNK == 256 == THREADS)
#pragma unroll
    for (int b = 0; b < BB; ++b)
        sp[t][b] = predicts[b * L + i0 + t];
    __syncthreads();

    const int*   mp = mask + (size_t)i0 * L + j;  // next mask batch to load
    const float* ap = adj  + (size_t)i0 * L + j;  // next adj batch to gather

    int   m_gather[RB];   // masks for the batch to gather next
    int   m_new[RB];      // masks in flight
    float a_cur[RB];      // adj values (in flight) for batch to consume
    float a_next[RB];

    // ---- prologue ----
    int m_A[RB];
#pragma unroll
    for (int r = 0; r < RB; ++r) m_A[r] = __ldcs(mp + (size_t)r * L);   // batch 0
    mp += (size_t)RB * L;
#pragma unroll
    for (int r = 0; r < RB; ++r) m_gather[r] = __ldcs(mp + (size_t)r * L); // batch 1
    mp += (size_t)RB * L;
#pragma unroll
    for (int r = 0; r < RB; ++r)
        a_cur[r] = m_A[r] ? __ldcs(ap + (size_t)r * L) : -1.0f;         // adj batch 0
    ap += (size_t)RB * L;

    // ---- steady state ----
    for (int batch = 0; batch < NB; ++batch) {
        const int ii = batch * RB;

        if (batch + 1 < NB) {
            // gather adj for batch+1 (masks already arrived)
#pragma unroll
            for (int r = 0; r < RB; ++r)
                a_next[r] = m_gather[r] ? __ldcs(ap + (size_t)r * L) : -1.0f;
            ap += (size_t)RB * L;
        }
        if (batch + 2 < NB) {
            // mask loads for batch+2
#pragma unroll
            for (int r = 0; r < RB; ++r)
                m_new[r] = __ldcs(mp + (size_t)r * L);
            mp += (size_t)RB * L;
        }

        // consume batch (a_cur issued one iteration ago — latency hidden)
#pragma unroll
        for (int r = 0; r < RB; ++r) {
            const float a = a_cur[r];
            if (a >= 0.0f) {
                cnt += 1.f;
                const float4 lo = *(const float4*)&sp[ii + r][0];
                const float4 hi = *(const float4*)&sp[ii + r][4];
                acc[0] = fmaf(lo.x, a, acc[0]);
                acc[1] = fmaf(lo.y, a, acc[1]);
                acc[2] = fmaf(lo.z, a, acc[2]);
                acc[3] = fmaf(lo.w, a, acc[3]);
                acc[4] = fmaf(hi.x, a, acc[4]);
                acc[5] = fmaf(hi.y, a, acc[5]);
                acc[6] = fmaf(hi.z, a, acc[6]);
                acc[7] = fmaf(hi.w, a, acc[7]);
            }
        }

#pragma unroll
        for (int r = 0; r < RB; ++r) {
            a_cur[r]    = a_next[r];
            m_gather[r] = m_new[r];
        }
    }

    g_cnt[chunk][j] = cnt;
#pragma unroll
    for (int b = 0; b < BB; ++b)
        g_part[chunk][b][j] = acc[b];
}

// ---------------------------------------------------------------------------
// Pass 2: thread = (b, j) pair. 256 threads = 8 b-groups x 32 j-lanes.
// ---------------------------------------------------------------------------
__global__ __launch_bounds__(256)
void pass2_kernel(const float* __restrict__ predicts,
                  const float* __restrict__ sim,
                  const int* __restrict__ mask) {
    __shared__ float ssim[BB * BB];
    __shared__ float scand[BB][33];
    __shared__ float sadd[32], sinv[32];

    const int t  = threadIdx.x;
    const int b  = t >> 5;
    const int jl = t & 31;
    const int j  = blockIdx.x * 32 + jl;

    if (t < BB * BB) ssim[t] = sim[t];

    if (b == 0) {
        float cnt = 0.f;
#pragma unroll
        for (int c = 0; c < NI; ++c) cnt += g_cnt[c][j];
        const float mjj = mask[(size_t)j * (L + 1)] ? 1.f : 0.f;
        const float add = 1.f - mjj;
        sadd[jl] = add;
        sinv[jl] = 1.f / (cnt + add);
    }

    float acc = 0.f;
#pragma unroll
    for (int c = 0; c < NI; ++c) acc += g_part[c][b][j];
    const float p = predicts[b * L + j];
    __syncthreads();

    const float cand = (acc + p * sadd[jl]) * sinv[jl];
    scand[b][jl] = cand;
    __syncthreads();

    float d = p;
#pragma unroll
    for (int k = 0; k < BB; ++k) d -= ssim[b * BB + k] * scand[k][jl];
    float ss = d * d;

#pragma unroll
    for (int o = 16; o > 0; o >>= 1) ss += __shfl_down_sync(0xffffffffu, ss, o);
    if (jl == 0) g_bpart[blockIdx.x][b] = ss;
}

// ---------------------------------------------------------------------------
// Pass 3: final reduce: norms = sqrt(sumsq), valid mask, mean over valid.
// ---------------------------------------------------------------------------
__global__ __launch_bounds__(256)
void pass3_kernel(const float* __restrict__ sim, float* __restrict__ out) {
    __shared__ float norms[BB];
    const int w    = threadIdx.x >> 5;
    const int lane = threadIdx.x & 31;

    if (w < BB) {
        float s = 0.f;
        for (int i = lane; i < GX2; i += 32) s += g_bpart[i][w];
#pragma unroll
        for (int o = 16; o > 0; o >>= 1) s += __shfl_down_sync(0xffffffffu, s, o);
        if (lane == 0) norms[w] = sqrtf(s);
    }
    __syncthreads();

    if (threadIdx.x == 0) {
        float total = 0.f, c = 0.f;
        for (int b = 0; b < BB; ++b) {
            float rs = 0.f;
            for (int k = 0; k < BB; ++k) rs += sim[b * BB + k];
            if (rs != 0.f) { c += 1.f; total += norms[b]; }
        }
        out[0] = (c == 0.f) ? 0.f : total / fmaxf(c, 1.f);
    }
}

// ---------------------------------------------------------------------------
extern "C" void kernel_launch(void* const* d_in, const int* in_sizes, int n_in,
                              void* d_out, int out_size) {
    (void)in_sizes; (void)n_in; (void)out_size;
    const float* predicts = (const float*)d_in[0];   // [8, L]
    const float* sim      = (const float*)d_in[1];   // [8, 8]
    const float* adj      = (const float*)d_in[2];   // [L, L]
    const int*   mask     = (const int*)d_in[3];     // [L, L] bool->int32
    float* out = (float*)d_out;

    dim3 g1(GX, NI);
    pass1_kernel<<<g1, THREADS>>>(predicts, adj, mask);
    pass2_kernel<<<GX2, 256>>>(predicts, sim, mask);
    pass3_kernel<<<1, 256>>>(sim, out);
}